// round 7
// baseline (speedup 1.0000x reference)
#include <cuda_runtime.h>
#include <cuda_fp16.h>
#include <math.h>

#define Bn   256
#define IC   1152
#define En   8
#define NC   10
#define DV   16
#define JD   160     // NC*DV

// hat kernel tiling
#define HK_ICHUNK 32
#define HK_NCHUNK (IC / HK_ICHUNK)   // 36
#define HK_BTILE  32
#define HK_NBT    (Bn / HK_BTILE)    // 8

// routing kernel: 384 threads = 48 octets; each octet owns i = oct + 48*t
#define RT_THREADS 384
#define RT_WARPS   12
#define I_PER_OCT  (IC / 48)         // 24

// Scratch (static device arrays; no cudaMalloc allowed)
__device__ __half g_hat[(size_t)Bn * IC * JD];            // 94.4 MB (L2-resident)
__device__ float  g_Wt[(size_t)IC * JD * En];             // W transposed: [i][jd][e]
__device__ float  g_c0[(size_t)IC * NC];                  // softmax(bias) per i
__device__ float  g_part0[(size_t)Bn * HK_NCHUNK * JD];   // pass-0 partials

// ---------------------------------------------------------------------------
// Kernel 0: transpose W[i,j,e,d] -> Wt[i, jd, e]; also c0[i,:] = softmax(bias[i,:])
// ---------------------------------------------------------------------------
__global__ __launch_bounds__(128) void transpose_W(
    const float* __restrict__ W, const float* __restrict__ bias)
{
    const int i = blockIdx.x;
    __shared__ float sw[1280 + 80];
    const float* Wi = W + (size_t)i * (NC * En * DV);
#pragma unroll
    for (int o = threadIdx.x; o < NC * En * DV; o += 128)
        sw[o + (o >> 4)] = __ldg(Wi + o);

    if (threadIdx.x < 16) {
        const int l = threadIdx.x;
        float e = (l < NC) ? __expf(__ldg(&bias[i * NC + l])) : 0.f;
        float se = e;
#pragma unroll
        for (int off = 1; off < 16; off <<= 1)
            se += __shfl_xor_sync(0xffffu, se, off);
        if (l < NC) g_c0[i * NC + l] = e * __fdividef(1.f, se);
    }
    __syncthreads();
    float* Wo = g_Wt + (size_t)i * (JD * En);
#pragma unroll
    for (int o = threadIdx.x; o < JD * En; o += 128) {
        const int e = o & 7, jd = o >> 3;
        const int src = (jd >> 4) * (En * DV) + e * DV + (jd & 15);
        Wo[o] = sw[src + (src >> 4)];
    }
}

// ---------------------------------------------------------------------------
// Kernel 1: hat[b,i,jd] = sum_e x[b,i,e]*Wt[i,jd,e] -> fp16 (L2-resident)
// + pass-0 partials with precomputed c0.
// ---------------------------------------------------------------------------
__global__ __launch_bounds__(256, 2) void hat_s0_kernel(const float* __restrict__ x)
{
    const int chunk = blockIdx.x;
    const int bt    = blockIdx.y;
    const int tid   = threadIdx.x;
    const int w     = tid >> 5;
    const int lane  = tid & 31;
    const int i0    = chunk * HK_ICHUNK;
    const int b0    = bt * HK_BTILE + w * 4;

    const int jds[5] = {2 * lane, 2 * lane + 1, 64 + 2 * lane, 65 + 2 * lane, 128 + lane};

    float acc[4][5];
#pragma unroll
    for (int bb = 0; bb < 4; bb++)
#pragma unroll
        for (int k = 0; k < 5; k++) acc[bb][k] = 0.f;

    for (int il = 0; il < HK_ICHUNK; il++) {
        const int i = i0 + il;

        float wv[5][8];
        const float4* wp = reinterpret_cast<const float4*>(g_Wt + (size_t)i * (JD * En));
#pragma unroll
        for (int k = 0; k < 5; k++) {
            const float4 a = __ldg(wp + jds[k] * 2);
            const float4 c = __ldg(wp + jds[k] * 2 + 1);
            wv[k][0]=a.x; wv[k][1]=a.y; wv[k][2]=a.z; wv[k][3]=a.w;
            wv[k][4]=c.x; wv[k][5]=c.y; wv[k][6]=c.z; wv[k][7]=c.w;
        }

        const float c0a = __ldg(&g_c0[i * NC + (lane >> 3)]);
        const float c0b = __ldg(&g_c0[i * NC + 4 + (lane >> 3)]);
        const float c0c = __ldg(&g_c0[i * NC + 8 + (lane >> 4)]);
        const float c0v[5] = {c0a, c0a, c0b, c0b, c0c};

#pragma unroll
        for (int bb = 0; bb < 4; bb++) {
            const int b = b0 + bb;
            const float4* xp =
                reinterpret_cast<const float4*>(x + ((size_t)b * IC + i) * En);
            const float4 x0 = __ldg(xp);
            const float4 x1 = __ldg(xp + 1);
            const float xv[8] = {x0.x, x0.y, x0.z, x0.w, x1.x, x1.y, x1.z, x1.w};

            float s[5];
#pragma unroll
            for (int k = 0; k < 5; k++) {
                float t = 0.f;
#pragma unroll
                for (int e = 0; e < En; e++) t = fmaf(xv[e], wv[k][e], t);
                s[k] = t;
                acc[bb][k] = fmaf(c0v[k], t, acc[bb][k]);
            }
            __half* hp = g_hat + ((size_t)b * IC + i) * JD;
            *reinterpret_cast<__half2*>(hp + 2 * lane)      = __floats2half2_rn(s[0], s[1]);
            *reinterpret_cast<__half2*>(hp + 64 + 2 * lane) = __floats2half2_rn(s[2], s[3]);
            hp[128 + lane] = __float2half_rn(s[4]);
        }
    }

#pragma unroll
    for (int bb = 0; bb < 4; bb++) {
        float* pp = g_part0 + ((size_t)(b0 + bb) * HK_NCHUNK + chunk) * JD;
#pragma unroll
        for (int k = 0; k < 5; k++) pp[jds[k]] = acc[bb][k];
    }
}

// ---------------------------------------------------------------------------
// Kernel 2: all routing for one b. Octet-per-i, register-resident rows:
// 8 threads own one i; thread h owns j=h (+ j=8+h if h<2). Row loaded ONCE
// per pass via coalesced LDG.128 (warp = 4 consecutive rows), agreement in
// half2 regs, octet softmax via 3 shuffles, fp32 register accumulators.
// No smem / no barriers in the mainloop.
// ---------------------------------------------------------------------------
extern __shared__ float bias_s[];   // IC*NC floats (46080 B, dynamic)

__global__ __launch_bounds__(RT_THREADS, 2) void route_kernel(
    const float* __restrict__ bias, float* __restrict__ out)
{
    __shared__ float sred[RT_WARPS * JD];      // 7680 B
    __shared__ float s_sm[JD], u_f[JD], scale_sm[NC];
    __shared__ __align__(16) __half2 us2[JD / 2];

    const int b    = blockIdx.x;
    const int tid  = threadIdx.x;
    const int w    = tid >> 5;
    const int lane = tid & 31;
    const int h    = lane & 7;          // j-slot within octet
    const int oct  = w * 4 + (lane >> 3);  // 0..47
    const bool two = (h < 2);
    const int j0   = h, j1 = 8 + h;

    // stage bias (read once, coalesced)
    for (int o = tid; o < IC * NC; o += RT_THREADS) bias_s[o] = __ldg(bias + o);

    // ---- v0 = squash(sum of pass-0 partials) ----
    if (tid < JD) {
        float s = 0.f;
#pragma unroll
        for (int c = 0; c < HK_NCHUNK; c++)
            s += g_part0[((size_t)b * HK_NCHUNK + c) * JD + tid];
        s_sm[tid] = s;
    }
    __syncthreads();
    if (tid < NC) {
        float s2 = 0.f;
#pragma unroll
        for (int d = 0; d < DV; d++) { float v = s_sm[tid * DV + d]; s2 = fmaf(v, v, s2); }
        scale_sm[tid] = s2 / (1.0f + s2) * rsqrtf(s2);
    }
    __syncthreads();
    if (tid < JD) u_f[tid] = scale_sm[tid >> 4] * s_sm[tid];
    __syncthreads();
    if (tid < JD / 2) us2[tid] = __floats2half2_rn(u_f[2 * tid], u_f[2 * tid + 1]);
    __syncthreads();

    const __half* hb = g_hat + (size_t)b * IC * JD;

    for (int pass = 0; pass < 2; pass++) {
        // u slices for this thread's j's -> registers
        __half2 u0[8], u1[8];
#pragma unroll
        for (int m = 0; m < 8; m++) u0[m] = us2[j0 * 8 + m];
#pragma unroll
        for (int m = 0; m < 8; m++) u1[m] = us2[j1 * 8 + m];

        float acc0[16], acc1[16];
#pragma unroll
        for (int d = 0; d < 16; d++) { acc0[d] = 0.f; acc1[d] = 0.f; }

        for (int t = 0; t < I_PER_OCT; t++) {
            const int i = oct + 48 * t;
            const uint4* rp = reinterpret_cast<const uint4*>(hb + (size_t)i * JD);

            // row slices (all independent loads -> deep MLP)
            const uint4 q0 = __ldg(rp + 2 * j0);
            const uint4 q1 = __ldg(rp + 2 * j0 + 1);
            uint4 r0, r1;
            if (two) { r0 = __ldg(rp + 2 * j1); r1 = __ldg(rp + 2 * j1 + 1); }

            // agreement dots (half2)
            const __half2* a0 = reinterpret_cast<const __half2*>(&q0);
            const __half2* a1 = reinterpret_cast<const __half2*>(&q1);
            __half2 d2 = __float2half2_rn(0.f);
#pragma unroll
            for (int m = 0; m < 4; m++) d2 = __hfma2(a0[m], u0[m], d2);
#pragma unroll
            for (int m = 0; m < 4; m++) d2 = __hfma2(a1[m], u0[4 + m], d2);
            const float e0 = __expf(__low2float(d2) + __high2float(d2) +
                                    bias_s[i * NC + j0]);
            float e1 = 0.f;
            if (two) {
                const __half2* b0p = reinterpret_cast<const __half2*>(&r0);
                const __half2* b1p = reinterpret_cast<const __half2*>(&r1);
                __half2 f2 = __float2half2_rn(0.f);
#pragma unroll
                for (int m = 0; m < 4; m++) f2 = __hfma2(b0p[m], u1[m], f2);
#pragma unroll
                for (int m = 0; m < 4; m++) f2 = __hfma2(b1p[m], u1[4 + m], f2);
                e1 = __expf(__low2float(f2) + __high2float(f2) +
                            bias_s[i * NC + j1]);
            }

            // octet softmax: sum over 8 lanes (j coverage 8*1 + 2 = 10)
            float se = e0 + e1;
            se += __shfl_xor_sync(0xffffffffu, se, 1);
            se += __shfl_xor_sync(0xffffffffu, se, 2);
            se += __shfl_xor_sync(0xffffffffu, se, 4);
            const float inv = __fdividef(1.f, se);
            const float c0 = e0 * inv;
            const float c1 = e1 * inv;

            // weighted accumulate (rows still in registers)
#pragma unroll
            for (int m = 0; m < 4; m++) {
                const float2 fa = __half22float2(reinterpret_cast<const __half2*>(&q0)[m]);
                const float2 fb = __half22float2(reinterpret_cast<const __half2*>(&q1)[m]);
                acc0[2 * m]     = fmaf(c0, fa.x, acc0[2 * m]);
                acc0[2 * m + 1] = fmaf(c0, fa.y, acc0[2 * m + 1]);
                acc0[8 + 2 * m]     = fmaf(c0, fb.x, acc0[8 + 2 * m]);
                acc0[8 + 2 * m + 1] = fmaf(c0, fb.y, acc0[8 + 2 * m + 1]);
            }
            if (two) {
#pragma unroll
                for (int m = 0; m < 4; m++) {
                    const float2 fa = __half22float2(reinterpret_cast<const __half2*>(&r0)[m]);
                    const float2 fb = __half22float2(reinterpret_cast<const __half2*>(&r1)[m]);
                    acc1[2 * m]     = fmaf(c1, fa.x, acc1[2 * m]);
                    acc1[2 * m + 1] = fmaf(c1, fa.y, acc1[2 * m + 1]);
                    acc1[8 + 2 * m]     = fmaf(c1, fb.x, acc1[8 + 2 * m]);
                    acc1[8 + 2 * m + 1] = fmaf(c1, fb.y, acc1[8 + 2 * m + 1]);
                }
            }
        }

        // ---- fold 4 octets within warp (lanes with same h share j) ----
#pragma unroll
        for (int d = 0; d < 16; d++) {
            acc0[d] += __shfl_xor_sync(0xffffffffu, acc0[d], 8);
            acc0[d] += __shfl_xor_sync(0xffffffffu, acc0[d], 16);
            acc1[d] += __shfl_xor_sync(0xffffffffu, acc1[d], 8);
            acc1[d] += __shfl_xor_sync(0xffffffffu, acc1[d], 16);
        }
        if (lane < 8) {
            float4* sp = reinterpret_cast<float4*>(&sred[w * JD + j0 * DV]);
#pragma unroll
            for (int m = 0; m < 4; m++)
                sp[m] = make_float4(acc0[4 * m], acc0[4 * m + 1],
                                    acc0[4 * m + 2], acc0[4 * m + 3]);
            if (two) {
                float4* sq = reinterpret_cast<float4*>(&sred[w * JD + j1 * DV]);
#pragma unroll
                for (int m = 0; m < 4; m++)
                    sq[m] = make_float4(acc1[4 * m], acc1[4 * m + 1],
                                        acc1[4 * m + 2], acc1[4 * m + 3]);
            }
        }
        __syncthreads();

        // ---- cross-warp reduce + squash ----
        if (tid < JD) {
            float s = 0.f;
#pragma unroll
            for (int w2 = 0; w2 < RT_WARPS; w2++) s += sred[w2 * JD + tid];
            s_sm[tid] = s;
        }
        __syncthreads();
        if (tid < NC) {
            float s2 = 0.f;
#pragma unroll
            for (int d = 0; d < DV; d++) { float v = s_sm[tid * DV + d]; s2 = fmaf(v, v, s2); }
            scale_sm[tid] = s2 / (1.0f + s2) * rsqrtf(s2);
        }
        __syncthreads();
        if (tid < JD) {
            const float v = scale_sm[tid >> 4] * s_sm[tid];
            if (pass == 0) u_f[tid] += v;                 // u = v0 + v1 (telescoped)
            else           out[(size_t)b * JD + tid] = v; // final v2
        }
        __syncthreads();
        if (pass == 0 && tid < JD / 2)
            us2[tid] = __floats2half2_rn(u_f[2 * tid], u_f[2 * tid + 1]);
        __syncthreads();
    }
}

// ---------------------------------------------------------------------------
extern "C" void kernel_launch(void* const* d_in, const int* in_sizes, int n_in,
                              void* d_out, int out_size)
{
    const float* x    = (const float*)d_in[0];
    const float* W    = (const float*)d_in[1];
    const float* bias = (const float*)d_in[2];
    float* out        = (float*)d_out;

    cudaFuncSetAttribute(route_kernel,
                         cudaFuncAttributeMaxDynamicSharedMemorySize,
                         IC * NC * (int)sizeof(float));

    transpose_W<<<IC, 128>>>(W, bias);
    hat_s0_kernel<<<dim3(HK_NCHUNK, HK_NBT), 256>>>(x);
    route_kernel<<<Bn, RT_THREADS, IC * NC * sizeof(float)>>>(bias, out);
}

// round 8
// speedup vs baseline: 1.1596x; 1.1596x over previous
#include <cuda_runtime.h>
#include <cuda_fp16.h>
#include <cuda_pipeline.h>
#include <math.h>

#define Bn   256
#define IC   1152
#define En   8
#define NC   10
#define DV   16
#define JD   160     // NC*DV

// hat kernel tiling
#define HK_ICHUNK 32
#define HK_NCHUNK (IC / HK_ICHUNK)   // 36
#define HK_BTILE  32
#define HK_NBT    (Bn / HK_BTILE)    // 8

// routing kernel (R5 structure)
#define RT_THREADS 384
#define RT_WARPS   12
#define CH         96
#define NCHUNKS    (IC / CH)         // 12
#define ROWU4      21                // uint4 per padded smem row
#define ROWH       168
#define U4_PER_BUF (CH * ROWU4)
#define SMH_BYTES  (2 * U4_PER_BUF * 16)

// Scratch (static device arrays; no cudaMalloc allowed)
__device__ __half g_hat[(size_t)Bn * IC * JD];            // 94.4 MB (L2-resident)
__device__ __half g_Wt2[(size_t)IC * 5 * 32 * 8];         // lane-interleaved fp16 W
__device__ __half g_xh[(size_t)Bn * IC * En];             // x in fp16
__device__ float  g_c0[(size_t)IC * NC];                  // softmax(bias) per i
__device__ float  g_part0[(size_t)Bn * HK_NCHUNK * JD];   // pass-0 partials

// ---------------------------------------------------------------------------
// Kernel A: x -> fp16
// ---------------------------------------------------------------------------
__global__ __launch_bounds__(256) void xcvt_kernel(const float* __restrict__ x)
{
    const int idx = blockIdx.x * 256 + threadIdx.x;   // over float4s
    if (idx < Bn * IC * En / 4) {
        const float4 v = __ldg(reinterpret_cast<const float4*>(x) + idx);
        __half2* o = reinterpret_cast<__half2*>(g_xh) + 2 * idx;
        o[0] = __floats2half2_rn(v.x, v.y);
        o[1] = __floats2half2_rn(v.z, v.w);
    }
}

// ---------------------------------------------------------------------------
// Kernel B: build Wt2 fp16 lane-interleaved layout + c0 = softmax(bias).
// Chunk c<4: half s -> jd = (c<2?0:64) + 2*lane + (s&1), e = (c&1)*4 + (s>>1)
//   (half2 m of chunk pair = (W(jd0,e), W(jd1,e)))
// Chunk c==4: half s -> jd = 128+lane, e = s (adjacent e-pairs).
// ---------------------------------------------------------------------------
__global__ __launch_bounds__(160) void prep_W(
    const float* __restrict__ W, const float* __restrict__ bias)
{
    const int i = blockIdx.x;
    __shared__ float sw[1280 + 80];
    const float* Wi = W + (size_t)i * 1280;
    for (int o = threadIdx.x; o < 1280; o += 160)
        sw[o + (o >> 4)] = __ldg(Wi + o);

    if (threadIdx.x < 16) {
        const int l = threadIdx.x;
        float e = (l < NC) ? __expf(__ldg(&bias[i * NC + l])) : 0.f;
        float se = e;
#pragma unroll
        for (int off = 1; off < 16; off <<= 1)
            se += __shfl_xor_sync(0xffffu, se, off);
        if (l < NC) g_c0[i * NC + l] = e * __fdividef(1.f, se);
    }
    __syncthreads();

    const int c = threadIdx.x >> 5, lane = threadIdx.x & 31;
    __half h[8];
#pragma unroll
    for (int s = 0; s < 8; s++) {
        int jd, e;
        if (c < 4) { jd = (c < 2 ? 0 : 64) + 2 * lane + (s & 1); e = (c & 1) * 4 + (s >> 1); }
        else       { jd = 128 + lane; e = s; }
        const int j = jd >> 4, d = jd & 15;
        const int src = (j * 8 + e) * 16 + d;
        h[s] = __float2half_rn(sw[src + (src >> 4)]);
    }
    *reinterpret_cast<uint4*>(g_Wt2 + (((size_t)i * 5 + c) * 32 + lane) * 8) =
        *reinterpret_cast<const uint4*>(h);
}

// ---------------------------------------------------------------------------
// Kernel C: hat via HFMA2 with coalesced W loads. Lane owns jd slots
// {2l,2l+1, 64+2l,65+2l, 128+l}; results come out as half2 store units.
// Pass-0 partials: half2 accumulation, fp32 flush every 8 i's.
// ---------------------------------------------------------------------------
__global__ __launch_bounds__(256, 2) void hat_s0_kernel()
{
    const int chunk = blockIdx.x;          // 0..35
    const int bt    = blockIdx.y;          // 0..7
    const int tid   = threadIdx.x;
    const int w     = tid >> 5;
    const int lane  = tid & 31;
    const int i0    = chunk * HK_ICHUNK;
    const int b0    = bt * HK_BTILE + w * 4;

    float acc[4][5];
#pragma unroll
    for (int bb = 0; bb < 4; bb++)
#pragma unroll
        for (int k = 0; k < 5; k++) acc[bb][k] = 0.f;

    const __half2 z2 = __float2half2_rn(0.f);

    for (int il8 = 0; il8 < HK_ICHUNK / 8; il8++) {
        __half2 acc2[4][3];
#pragma unroll
        for (int bb = 0; bb < 4; bb++)
#pragma unroll
            for (int g = 0; g < 3; g++) acc2[bb][g] = z2;

        for (int il = 0; il < 8; il++) {
            const int i = i0 + il8 * 8 + il;

            // W: 5 coalesced LDG.128 (lanes contiguous 16B)
            uint4 wq[5];
            const uint4* wp = reinterpret_cast<const uint4*>(g_Wt2 + (size_t)i * 1280);
#pragma unroll
            for (int c = 0; c < 5; c++) wq[c] = __ldg(wp + c * 32 + lane);
            const __half2* a2 = reinterpret_cast<const __half2*>(&wq[0]);   // 8 (A)
            const __half2* b2 = a2 + 8;                                     // 8 (B)
            const __half2* c4 = a2 + 16;                                    // 4 (C)

            const __half2 c0a2 = __float2half2_rn(__ldg(&g_c0[i * NC + (lane >> 3)]));
            const __half2 c0b2 = __float2half2_rn(__ldg(&g_c0[i * NC + 4 + (lane >> 3)]));
            const __half2 c0c2 = __float2half2_rn(__ldg(&g_c0[i * NC + 8 + (lane >> 4)]));

#pragma unroll
            for (int bb = 0; bb < 4; bb++) {
                const int b = b0 + bb;
                const uint4 xq = __ldg(reinterpret_cast<const uint4*>(
                    g_xh + ((size_t)b * IC + i) * En));
                const __half2* x2 = reinterpret_cast<const __half2*>(&xq);

                __half2 sA0 = z2, sA1 = z2, sB0 = z2, sB1 = z2, sC0 = z2, sC1 = z2;
#pragma unroll
                for (int m = 0; m < 2; m++) {
                    const __half2 xl = __low2half2(x2[m]);
                    const __half2 xh = __high2half2(x2[m]);
                    sA0 = __hfma2(xl, a2[2 * m], sA0);
                    sA0 = __hfma2(xh, a2[2 * m + 1], sA0);
                    sB0 = __hfma2(xl, b2[2 * m], sB0);
                    sB0 = __hfma2(xh, b2[2 * m + 1], sB0);
                    sC0 = __hfma2(x2[m], c4[m], sC0);
                }
#pragma unroll
                for (int m = 2; m < 4; m++) {
                    const __half2 xl = __low2half2(x2[m]);
                    const __half2 xh = __high2half2(x2[m]);
                    sA1 = __hfma2(xl, a2[2 * m], sA1);
                    sA1 = __hfma2(xh, a2[2 * m + 1], sA1);
                    sB1 = __hfma2(xl, b2[2 * m], sB1);
                    sB1 = __hfma2(xh, b2[2 * m + 1], sB1);
                    sC1 = __hfma2(x2[m], c4[m], sC1);
                }
                const __half2 sA = __hadd2(sA0, sA1);
                const __half2 sB = __hadd2(sB0, sB1);
                const __half2 sC = __hadd2(sC0, sC1);   // (even-e, odd-e partials)

                __half* hp = g_hat + ((size_t)b * IC + i) * JD;
                *reinterpret_cast<__half2*>(hp + 2 * lane)      = sA;
                *reinterpret_cast<__half2*>(hp + 64 + 2 * lane) = sB;
                hp[128 + lane] = __hadd(__low2half(sC), __high2half(sC));

                acc2[bb][0] = __hfma2(c0a2, sA, acc2[bb][0]);
                acc2[bb][1] = __hfma2(c0b2, sB, acc2[bb][1]);
                acc2[bb][2] = __hfma2(c0c2, sC, acc2[bb][2]);
            }
        }

        // flush half2 partials -> fp32
#pragma unroll
        for (int bb = 0; bb < 4; bb++) {
            const float2 fa = __half22float2(acc2[bb][0]);
            const float2 fb = __half22float2(acc2[bb][1]);
            const float2 fc = __half22float2(acc2[bb][2]);
            acc[bb][0] += fa.x; acc[bb][1] += fa.y;
            acc[bb][2] += fb.x; acc[bb][3] += fb.y;
            acc[bb][4] += fc.x + fc.y;
        }
    }

#pragma unroll
    for (int bb = 0; bb < 4; bb++) {
        float* pp = g_part0 + ((size_t)(b0 + bb) * HK_NCHUNK + chunk) * JD;
        pp[2 * lane]      = acc[bb][0];
        pp[2 * lane + 1]  = acc[bb][1];
        pp[64 + 2 * lane] = acc[bb][2];
        pp[65 + 2 * lane] = acc[bb][3];
        pp[128 + lane]    = acc[bb][4];
    }
}

// ---------------------------------------------------------------------------
// Kernel D: routing (R5 structure — best measured variant).
// ---------------------------------------------------------------------------
extern __shared__ uint4 smu4[];

__device__ __forceinline__ void load_chunk(int b, int ch, int buf, int tid)
{
    const uint4* src =
        reinterpret_cast<const uint4*>(g_hat + ((size_t)b * IC + ch * CH) * JD);
    uint4* dst = smu4 + buf * U4_PER_BUF;
#pragma unroll
    for (int k = 0; k < 5; k++) {
        const int q = tid + k * RT_THREADS;
        const int row = q / 20, col = q % 20;
        __pipeline_memcpy_async(dst + row * ROWU4 + col, src + q, 16);
    }
    __pipeline_commit();
}

__global__ __launch_bounds__(RT_THREADS, 2) void route_kernel(
    const float* __restrict__ bias, float* __restrict__ out)
{
    __shared__ float c_f[CH * NC];
    __shared__ float sred[RT_WARPS * JD];
    __shared__ float s_sm[JD], u_f[JD], scale_sm[NC];
    __shared__ __align__(16) __half2 us2[JD / 2];

    const int b    = blockIdx.x;
    const int tid  = threadIdx.x;
    const int w    = tid >> 5;
    const int lane = tid & 31;
    const int quad = tid >> 2;
    const int g    = tid & 3;
    const int jn   = (g < 2) ? 3 : 2;

    load_chunk(b, 0, 0, tid);

    if (tid < JD) {
        float s = 0.f;
#pragma unroll
        for (int c = 0; c < HK_NCHUNK; c++)
            s += g_part0[((size_t)b * HK_NCHUNK + c) * JD + tid];
        s_sm[tid] = s;
    }
    __syncthreads();
    if (tid < NC) {
        float s2 = 0.f;
#pragma unroll
        for (int d = 0; d < DV; d++) { float v = s_sm[tid * DV + d]; s2 = fmaf(v, v, s2); }
        scale_sm[tid] = s2 / (1.0f + s2) * rsqrtf(s2);
    }
    __syncthreads();
    if (tid < JD) u_f[tid] = scale_sm[tid >> 4] * s_sm[tid];
    __syncthreads();
    if (tid < JD / 2) us2[tid] = __floats2half2_rn(u_f[2 * tid], u_f[2 * tid + 1]);
    __syncthreads();

    for (int pass = 0; pass < 2; pass++) {
        float acc[5] = {0.f, 0.f, 0.f, 0.f, 0.f};

        for (int ch = 0; ch < NCHUNKS; ch++) {
            const int buf = ch & 1;
            if (ch + 1 < NCHUNKS) {
                load_chunk(b, ch + 1, (ch + 1) & 1, tid);
                __pipeline_wait_prior(1);
            } else {
                __pipeline_wait_prior(0);
            }
            __syncthreads();

            // Phase A: quad-per-i agreement + softmax
            {
                const uint4* row = smu4 + buf * U4_PER_BUF + quad * ROWU4;
                const int ig = ch * CH + quad;
                float av[3];
                float se = 0.f;
#pragma unroll
                for (int jj = 0; jj < 3; jj++) {
                    if (jj < jn) {
                        const int j = g + 4 * jj;
                        const uint4 q0 = row[2 * j];
                        const uint4 q1 = row[2 * j + 1];
                        const __half2* ha = reinterpret_cast<const __half2*>(&q0);
                        const __half2* hb = reinterpret_cast<const __half2*>(&q1);
                        __half2 a2 = __float2half2_rn(0.f);
#pragma unroll
                        for (int m = 0; m < 4; m++) a2 = __hfma2(ha[m], us2[j * 8 + m], a2);
#pragma unroll
                        for (int m = 0; m < 4; m++) a2 = __hfma2(hb[m], us2[j * 8 + 4 + m], a2);
                        av[jj] = __expf(__low2float(a2) + __high2float(a2) +
                                        __ldg(&bias[ig * NC + j]));
                        se += av[jj];
                    }
                }
                se += __shfl_xor_sync(0xffffffffu, se, 1);
                se += __shfl_xor_sync(0xffffffffu, se, 2);
                const float inv = __fdividef(1.f, se);
#pragma unroll
                for (int jj = 0; jj < 3; jj++)
                    if (jj < jn) c_f[quad * NC + g + 4 * jj] = av[jj] * inv;
            }
            __syncthreads();

            // Phase B: weighted sum, lane-owns-jd
            {
                const __half* hb0 = reinterpret_cast<const __half*>(
                    smu4 + buf * U4_PER_BUF + (w * 8) * ROWU4);
                const float* cb0 = c_f + (w * 8) * NC;
#pragma unroll
                for (int t = 0; t < 8; t++) {
                    const __half* hp = hb0 + t * ROWH;
                    const float*  cp = cb0 + t * NC;
#pragma unroll
                    for (int k = 0; k < 5; k++) {
                        const int jd = lane + 32 * k;
                        acc[k] = fmaf(cp[jd >> 4], __half2float(hp[jd]), acc[k]);
                    }
                }
            }
            __syncthreads();
        }

        if (pass == 0) load_chunk(b, 0, 0, tid);

#pragma unroll
        for (int k = 0; k < 5; k++) sred[w * JD + lane + 32 * k] = acc[k];
        __syncthreads();
        if (tid < JD) {
            float s = 0.f;
#pragma unroll
            for (int w2 = 0; w2 < RT_WARPS; w2++) s += sred[w2 * JD + tid];
            s_sm[tid] = s;
        }
        __syncthreads();
        if (tid < NC) {
            float s2 = 0.f;
#pragma unroll
            for (int d = 0; d < DV; d++) { float v = s_sm[tid * DV + d]; s2 = fmaf(v, v, s2); }
            scale_sm[tid] = s2 / (1.0f + s2) * rsqrtf(s2);
        }
        __syncthreads();
        if (tid < JD) {
            const float v = scale_sm[tid >> 4] * s_sm[tid];
            if (pass == 0) u_f[tid] += v;
            else           out[(size_t)b * JD + tid] = v;
        }
        __syncthreads();
        if (pass == 0 && tid < JD / 2)
            us2[tid] = __floats2half2_rn(u_f[2 * tid], u_f[2 * tid + 1]);
        __syncthreads();
    }
}

// ---------------------------------------------------------------------------
extern "C" void kernel_launch(void* const* d_in, const int* in_sizes, int n_in,
                              void* d_out, int out_size)
{
    const float* x    = (const float*)d_in[0];
    const float* W    = (const float*)d_in[1];
    const float* bias = (const float*)d_in[2];
    float* out        = (float*)d_out;

    cudaFuncSetAttribute(route_kernel,
                         cudaFuncAttributeMaxDynamicSharedMemorySize, SMH_BYTES);

    xcvt_kernel<<<(Bn * IC * En / 4 + 255) / 256, 256>>>(x);
    prep_W<<<IC, 160>>>(W, bias);
    hat_s0_kernel<<<dim3(HK_NCHUNK, HK_NBT), 256>>>();
    route_kernel<<<Bn, RT_THREADS, SMH_BYTES>>>(bias, out);
}

// round 9
// speedup vs baseline: 1.3185x; 1.1371x over previous
#include <cuda_runtime.h>
#include <cuda_fp16.h>
#include <cuda_pipeline.h>
#include <math.h>

#define Bn   256
#define IC   1152
#define En   8
#define NC   10
#define DV   16
#define JD   160     // NC*DV

// hat kernel tiling
#define HK_ICHUNK 32
#define HK_NCHUNK (IC / HK_ICHUNK)   // 36
#define HK_BTILE  32
#define HK_NBT    (Bn / HK_BTILE)    // 8

// routing kernel
#define RT_THREADS 384
#define RT_WARPS   12
#define CH         96
#define NCHUNKS    (IC / CH)         // 12
#define ROWU4      21                // uint4 per padded smem row
#define U4_PER_BUF (CH * ROWU4)
#define SMH_BYTES  (2 * U4_PER_BUF * 16)

// Scratch (static device arrays; no cudaMalloc allowed)
__device__ __half g_hat[(size_t)Bn * IC * JD];            // 94.4 MB (L2-resident)
__device__ __half g_Wt2[(size_t)IC * 5 * 32 * 8];         // lane-interleaved fp16 W
__device__ __half g_xh[(size_t)Bn * IC * En];             // x in fp16
__device__ float  g_c0[(size_t)IC * NC];                  // softmax(bias) per i
__device__ float  g_part0[(size_t)Bn * HK_NCHUNK * JD];   // pass-0 partials

// ---------------------------------------------------------------------------
// Kernel A: x -> fp16
// ---------------------------------------------------------------------------
__global__ __launch_bounds__(256) void xcvt_kernel(const float* __restrict__ x)
{
    const int idx = blockIdx.x * 256 + threadIdx.x;   // over float4s
    if (idx < Bn * IC * En / 4) {
        const float4 v = __ldg(reinterpret_cast<const float4*>(x) + idx);
        __half2* o = reinterpret_cast<__half2*>(g_xh) + 2 * idx;
        o[0] = __floats2half2_rn(v.x, v.y);
        o[1] = __floats2half2_rn(v.z, v.w);
    }
}

// ---------------------------------------------------------------------------
// Kernel B: Wt2 fp16 lane-interleaved layout (8 i's per block) + c0 softmax.
// Lane owns jd {4l..4l+3, 128+l}. Chunk c<4: pair p=c>>1, e-half=c&1;
//   half s -> jd = 4*lane + 2p + (s&1), e = 4*(c&1) + (s>>1).
// Chunk 4: half s -> jd = 128+lane, e = s.
// ---------------------------------------------------------------------------
__global__ __launch_bounds__(256) void prep_W(
    const float* __restrict__ W, const float* __restrict__ bias)
{
    const int i0 = blockIdx.x * 8;
    __shared__ float sw[8][1280 + 80];
    for (int o = threadIdx.x; o < 8 * 1280; o += 256) {
        const int il = o >> 10 >> 0; // placeholder (recomputed below)
        const int ii = o / 1280, k = o - ii * 1280;
        (void)il;
        sw[ii][k + (k >> 4)] = __ldg(W + (size_t)(i0 + ii) * 1280 + k);
    }
    if (threadIdx.x < 128) {
        const int il = threadIdx.x >> 4, l = threadIdx.x & 15;
        float e = (l < NC) ? __expf(__ldg(&bias[(i0 + il) * NC + l])) : 0.f;
        float se = e;
#pragma unroll
        for (int off = 1; off < 16; off <<= 1)
            se += __shfl_xor_sync(0xffffffffu, se, off, 16);
        if (l < NC) g_c0[(i0 + il) * NC + l] = e * __fdividef(1.f, se);
    }
    __syncthreads();

    const int wi = threadIdx.x >> 5, lane = threadIdx.x & 31;
    const int i = i0 + wi;
#pragma unroll
    for (int c = 0; c < 5; c++) {
        __half h[8];
#pragma unroll
        for (int s = 0; s < 8; s++) {
            int jd, e;
            if (c < 4) { jd = 4 * lane + 2 * (c >> 1) + (s & 1); e = 4 * (c & 1) + (s >> 1); }
            else       { jd = 128 + lane; e = s; }
            const int j = jd >> 4, d = jd & 15;
            const int src = (j * 8 + e) * 16 + d;
            h[s] = __float2half_rn(sw[wi][src + (src >> 4)]);
        }
        *reinterpret_cast<uint4*>(g_Wt2 + (((size_t)i * 5 + c) * 32 + lane) * 8) =
            *reinterpret_cast<const uint4*>(h);
    }
}

// ---------------------------------------------------------------------------
// Kernel C: hat via HFMA2. Lane owns jd {4l..4l+3, 128+l}: one shared j for
// the A-group (1 c0 load), stores = STG.64 + STG.U16, part0 = STG.128+STG.32.
// ---------------------------------------------------------------------------
__global__ __launch_bounds__(256, 2) void hat_s0_kernel()
{
    const int chunk = blockIdx.x;
    const int bt    = blockIdx.y;
    const int tid   = threadIdx.x;
    const int w     = tid >> 5;
    const int lane  = tid & 31;
    const int i0    = chunk * HK_ICHUNK;
    const int b0    = bt * HK_BTILE + w * 4;

    float acc[4][5];
#pragma unroll
    for (int bb = 0; bb < 4; bb++)
#pragma unroll
        for (int k = 0; k < 5; k++) acc[bb][k] = 0.f;

    const __half2 z2 = __float2half2_rn(0.f);

    for (int il8 = 0; il8 < HK_ICHUNK / 8; il8++) {
        __half2 acc2[4][3];
#pragma unroll
        for (int bb = 0; bb < 4; bb++)
#pragma unroll
            for (int g = 0; g < 3; g++) acc2[bb][g] = z2;

        for (int il = 0; il < 8; il++) {
            const int i = i0 + il8 * 8 + il;

            uint4 wq[5];
            const uint4* wp = reinterpret_cast<const uint4*>(g_Wt2 + (size_t)i * 1280);
#pragma unroll
            for (int c = 0; c < 5; c++) wq[c] = __ldg(wp + c * 32 + lane);
            const __half2* W2 = reinterpret_cast<const __half2*>(wq);  // [20]

            const __half2 c0A2 = __float2half2_rn(__ldg(&g_c0[i * NC + (lane >> 2)]));
            const __half2 c0C2 = __float2half2_rn(__ldg(&g_c0[i * NC + 8 + (lane >> 4)]));

#pragma unroll
            for (int bb = 0; bb < 4; bb++) {
                const int b = b0 + bb;
                const uint4 xq = __ldg(reinterpret_cast<const uint4*>(
                    g_xh + ((size_t)b * IC + i) * En));
                const __half2* x2 = reinterpret_cast<const __half2*>(&xq);
                const __half2 e0 = __low2half2(x2[0]), e1 = __high2half2(x2[0]);
                const __half2 e2 = __low2half2(x2[1]), e3 = __high2half2(x2[1]);
                const __half2 e4 = __low2half2(x2[2]), e5 = __high2half2(x2[2]);
                const __half2 e6 = __low2half2(x2[3]), e7 = __high2half2(x2[3]);

                __half2 sP[2];
#pragma unroll
                for (int p = 0; p < 2; p++) {
                    __half2 slo = __hmul2(e0, W2[8 * p]);
                    slo = __hfma2(e1, W2[8 * p + 1], slo);
                    slo = __hfma2(e2, W2[8 * p + 2], slo);
                    slo = __hfma2(e3, W2[8 * p + 3], slo);
                    __half2 shi = __hmul2(e4, W2[8 * p + 4]);
                    shi = __hfma2(e5, W2[8 * p + 5], shi);
                    shi = __hfma2(e6, W2[8 * p + 6], shi);
                    shi = __hfma2(e7, W2[8 * p + 7], shi);
                    sP[p] = __hadd2(slo, shi);
                }
                __half2 sC0 = __hmul2(x2[0], W2[16]);
                sC0 = __hfma2(x2[1], W2[17], sC0);
                __half2 sC1 = __hmul2(x2[2], W2[18]);
                sC1 = __hfma2(x2[3], W2[19], sC1);
                const __half2 sC = __hadd2(sC0, sC1);

                __half* hp = g_hat + ((size_t)b * IC + i) * JD;
                union { uint2 u; __half2 h[2]; } pk;
                pk.h[0] = sP[0]; pk.h[1] = sP[1];
                *reinterpret_cast<uint2*>(hp + 4 * lane) = pk.u;
                hp[128 + lane] = __hadd(__low2half(sC), __high2half(sC));

                acc2[bb][0] = __hfma2(c0A2, sP[0], acc2[bb][0]);
                acc2[bb][1] = __hfma2(c0A2, sP[1], acc2[bb][1]);
                acc2[bb][2] = __hfma2(c0C2, sC, acc2[bb][2]);
            }
        }

#pragma unroll
        for (int bb = 0; bb < 4; bb++) {
            const float2 fa = __half22float2(acc2[bb][0]);
            const float2 fb = __half22float2(acc2[bb][1]);
            const float2 fc = __half22float2(acc2[bb][2]);
            acc[bb][0] += fa.x; acc[bb][1] += fa.y;
            acc[bb][2] += fb.x; acc[bb][3] += fb.y;
            acc[bb][4] += fc.x + fc.y;
        }
    }

#pragma unroll
    for (int bb = 0; bb < 4; bb++) {
        float* pp = g_part0 + ((size_t)(b0 + bb) * HK_NCHUNK + chunk) * JD;
        *reinterpret_cast<float4*>(pp + 4 * lane) =
            make_float4(acc[bb][0], acc[bb][1], acc[bb][2], acc[bb][3]);
        pp[128 + lane] = acc[bb][4];
    }
}

// ---------------------------------------------------------------------------
// Kernel D: routing. R8 skeleton; Phase B vectorized (uint4 per lane,
// conflict-free per 8-lane LDS phase: banks (20*rB+4*gB)%32 distinct).
// ---------------------------------------------------------------------------
extern __shared__ uint4 smu4[];

__device__ __forceinline__ void load_chunk(int b, int ch, int buf, int tid)
{
    const uint4* src =
        reinterpret_cast<const uint4*>(g_hat + ((size_t)b * IC + ch * CH) * JD);
    uint4* dst = smu4 + buf * U4_PER_BUF;
#pragma unroll
    for (int k = 0; k < 5; k++) {
        const int q = tid + k * RT_THREADS;
        const int row = q / 20, col = q % 20;
        __pipeline_memcpy_async(dst + row * ROWU4 + col, src + q, 16);
    }
    __pipeline_commit();
}

__global__ __launch_bounds__(RT_THREADS, 2) void route_kernel(
    const float* __restrict__ bias, float* __restrict__ out)
{
    __shared__ float c_f[CH * NC];
    __shared__ float sred[RT_WARPS * JD];
    __shared__ float s_sm[JD], u_f[JD], scale_sm[NC];
    __shared__ __align__(16) __half2 us2[JD / 2];

    const int b    = blockIdx.x;
    const int tid  = threadIdx.x;
    const int w    = tid >> 5;
    const int lane = tid & 31;
    const int quad = tid >> 2;
    const int g    = tid & 3;
    const int jn   = (g < 2) ? 3 : 2;
    const int rB   = lane & 7;
    const int gB   = lane >> 3;

    load_chunk(b, 0, 0, tid);

    if (tid < JD) {
        float s = 0.f;
#pragma unroll
        for (int c = 0; c < HK_NCHUNK; c++)
            s += g_part0[((size_t)b * HK_NCHUNK + c) * JD + tid];
        s_sm[tid] = s;
    }
    __syncthreads();
    if (tid < NC) {
        float s2 = 0.f;
#pragma unroll
        for (int d = 0; d < DV; d++) { float v = s_sm[tid * DV + d]; s2 = fmaf(v, v, s2); }
        scale_sm[tid] = s2 / (1.0f + s2) * rsqrtf(s2);
    }
    __syncthreads();
    if (tid < JD) u_f[tid] = scale_sm[tid >> 4] * s_sm[tid];
    __syncthreads();
    if (tid < JD / 2) us2[tid] = __floats2half2_rn(u_f[2 * tid], u_f[2 * tid + 1]);
    __syncthreads();

    for (int pass = 0; pass < 2; pass++) {
        float acc[5][8];
#pragma unroll
        for (int m = 0; m < 5; m++)
#pragma unroll
            for (int d = 0; d < 8; d++) acc[m][d] = 0.f;

        for (int ch = 0; ch < NCHUNKS; ch++) {
            const int buf = ch & 1;
            if (ch + 1 < NCHUNKS) {
                load_chunk(b, ch + 1, (ch + 1) & 1, tid);
                __pipeline_wait_prior(1);
            } else {
                __pipeline_wait_prior(0);
            }
            __syncthreads();

            // Phase A: quad-per-i agreement + softmax
            {
                const uint4* row = smu4 + buf * U4_PER_BUF + quad * ROWU4;
                const int ig = ch * CH + quad;
                float av[3];
                float se = 0.f;
#pragma unroll
                for (int jj = 0; jj < 3; jj++) {
                    if (jj < jn) {
                        const int j = g + 4 * jj;
                        const uint4 q0 = row[2 * j];
                        const uint4 q1 = row[2 * j + 1];
                        const __half2* ha = reinterpret_cast<const __half2*>(&q0);
                        const __half2* hb = reinterpret_cast<const __half2*>(&q1);
                        __half2 a2 = __float2half2_rn(0.f);
#pragma unroll
                        for (int m = 0; m < 4; m++) a2 = __hfma2(ha[m], us2[j * 8 + m], a2);
#pragma unroll
                        for (int m = 0; m < 4; m++) a2 = __hfma2(hb[m], us2[j * 8 + 4 + m], a2);
                        av[jj] = __expf(__low2float(a2) + __high2float(a2) +
                                        __ldg(&bias[ig * NC + j]));
                        se += av[jj];
                    }
                }
                se += __shfl_xor_sync(0xffffffffu, se, 1);
                se += __shfl_xor_sync(0xffffffffu, se, 2);
                const float inv = __fdividef(1.f, se);
#pragma unroll
                for (int jj = 0; jj < 3; jj++)
                    if (jj < jn) c_f[quad * NC + g + 4 * jj] = av[jj] * inv;
            }
            __syncthreads();

            // Phase B: vectorized weighted sum (uint4 per lane)
            {
                const int row = w * 8 + rB;
                const uint4* rowp = smu4 + buf * U4_PER_BUF + row * ROWU4;
                const float* crow = c_f + row * NC;
#pragma unroll
                for (int m = 0; m < 5; m++) {
                    const int col = gB + 4 * m;
                    const uint4 q = rowp[col];
                    const float c = crow[col >> 1];
                    const __half2* h2 = reinterpret_cast<const __half2*>(&q);
#pragma unroll
                    for (int n = 0; n < 4; n++) {
                        const float2 f = __half22float2(h2[n]);
                        acc[m][2 * n]     = fmaf(c, f.x, acc[m][2 * n]);
                        acc[m][2 * n + 1] = fmaf(c, f.y, acc[m][2 * n + 1]);
                    }
                }
            }
            __syncthreads();
        }

        if (pass == 0) load_chunk(b, 0, 0, tid);

        // fold rows within warp (lanes sharing gB differ in rB = bits 0..2)
#pragma unroll
        for (int m = 0; m < 5; m++)
#pragma unroll
            for (int d = 0; d < 8; d++) {
#pragma unroll
                for (int off = 1; off < 8; off <<= 1)
                    acc[m][d] += __shfl_xor_sync(0xffffffffu, acc[m][d], off);
            }
        if (rB == 0) {
#pragma unroll
            for (int m = 0; m < 5; m++) {
                const int jd0 = 8 * (gB + 4 * m);
                *reinterpret_cast<float4*>(&sred[w * JD + jd0]) =
                    make_float4(acc[m][0], acc[m][1], acc[m][2], acc[m][3]);
                *reinterpret_cast<float4*>(&sred[w * JD + jd0 + 4]) =
                    make_float4(acc[m][4], acc[m][5], acc[m][6], acc[m][7]);
            }
        }
        __syncthreads();

        if (tid < JD) {
            float s = 0.f;
#pragma unroll
            for (int w2 = 0; w2 < RT_WARPS; w2++) s += sred[w2 * JD + tid];
            s_sm[tid] = s;
        }
        __syncthreads();
        if (tid < NC) {
            float s2 = 0.f;
#pragma unroll
            for (int d = 0; d < DV; d++) { float v = s_sm[tid * DV + d]; s2 = fmaf(v, v, s2); }
            scale_sm[tid] = s2 / (1.0f + s2) * rsqrtf(s2);
        }
        __syncthreads();
        if (tid < JD) {
            const float v = scale_sm[tid >> 4] * s_sm[tid];
            if (pass == 0) u_f[tid] += v;
            else           out[(size_t)b * JD + tid] = v;
        }
        __syncthreads();
        if (pass == 0 && tid < JD / 2)
            us2[tid] = __floats2half2_rn(u_f[2 * tid], u_f[2 * tid + 1]);
        __syncthreads();
    }
}

// ---------------------------------------------------------------------------
extern "C" void kernel_launch(void* const* d_in, const int* in_sizes, int n_in,
                              void* d_out, int out_size)
{
    const float* x    = (const float*)d_in[0];
    const float* W    = (const float*)d_in[1];
    const float* bias = (const float*)d_in[2];
    float* out        = (float*)d_out;

    cudaFuncSetAttribute(route_kernel,
                         cudaFuncAttributeMaxDynamicSharedMemorySize, SMH_BYTES);

    xcvt_kernel<<<(Bn * IC * En / 4 + 255) / 256, 256>>>(x);
    prep_W<<<IC / 8, 256>>>(W, bias);
    hat_s0_kernel<<<dim3(HK_NCHUNK, HK_NBT), 256>>>();
    route_kernel<<<Bn, RT_THREADS, SMH_BYTES>>>(bias, out);
}